// round 13
// baseline (speedup 1.0000x reference)
#include <cuda_runtime.h>
#include <cuda_bf16.h>
#include <cstdint>

#define D_MODEL 1024
#define N_HEADS 16
#define DKH     64
#define B_      4
#define T_      2048
#define M_TOT   (B_ * T_)        // 8192
#define N_QKV   (3 * D_MODEL)    // 3072
#define GK      1024

// ---------------- scratch (device globals; no allocation allowed) ----------
// GEMM operands, pre-split bf16 hi/lo:
__device__ __nv_bfloat16 g_xh[(size_t)M_TOT * GK];      // x        [M,K]
__device__ __nv_bfloat16 g_xl[(size_t)M_TOT * GK];
__device__ __nv_bfloat16 g_wqh[(size_t)N_QKV * GK];     // w_qkv^T  [N,K]
__device__ __nv_bfloat16 g_wql[(size_t)N_QKV * GK];
__device__ __nv_bfloat16 g_woh[(size_t)D_MODEL * GK];   // w_out^T  [N,K]
__device__ __nv_bfloat16 g_wol[(size_t)D_MODEL * GK];
__device__ __nv_bfloat16 g_ah[(size_t)M_TOT * GK];      // attn out [M,K]
__device__ __nv_bfloat16 g_al[(size_t)M_TOT * GK];
// Attention operands (written by gemm<0> epilogue), pre-split:
__device__ __nv_bfloat16 g_qh[(size_t)64 * T_ * DKH];   // [bh][t][dk], pre-scaled
__device__ __nv_bfloat16 g_ql[(size_t)64 * T_ * DKH];
__device__ __nv_bfloat16 g_kh[(size_t)64 * T_ * DKH];
__device__ __nv_bfloat16 g_kl[(size_t)64 * T_ * DKH];
__device__ __nv_bfloat16 g_vh[(size_t)64 * DKH * T_];   // V^T [bh][dk][t]
__device__ __nv_bfloat16 g_vl[(size_t)64 * DKH * T_];

// ============================ helpers ======================================
#define MMA_BF16(D, A, b0, b1) \
    asm volatile("mma.sync.aligned.m16n8k16.row.col.f32.bf16.bf16.f32 " \
        "{%0,%1,%2,%3}, {%4,%5,%6,%7}, {%8,%9}, {%0,%1,%2,%3};" \
        : "+f"((D)[0]), "+f"((D)[1]), "+f"((D)[2]), "+f"((D)[3]) \
        : "r"((A)[0]), "r"((A)[1]), "r"((A)[2]), "r"((A)[3]), "r"(b0), "r"(b1))

__device__ __forceinline__ void bf16_split(float x, unsigned short& h, unsigned short& l)
{
    __nv_bfloat16 hb = __float2bfloat16(x);
    h = __bfloat16_as_ushort(hb);
    l = __bfloat16_as_ushort(__float2bfloat16(x - __bfloat162float(hb)));
}
__device__ __forceinline__ void split2(float a, float b, uint32_t& hi, uint32_t& lo)
{
    unsigned short ha, la, hb, lb;
    bf16_split(a, ha, la);
    bf16_split(b, hb, lb);
    hi = (uint32_t)ha | ((uint32_t)hb << 16);
    lo = (uint32_t)la | ((uint32_t)lb << 16);
}

// ===================== convert / split kernels =============================
// x fp32 -> g_xh/g_xl (globals referenced INSIDE the kernel, not via args)
__global__ __launch_bounds__(256)
void cvt_split(const float* __restrict__ in, int n4)
{
    int i = blockIdx.x * 256 + threadIdx.x;
    if (i >= n4) return;
    float4 v = ((const float4*)in)[i];
    uint32_t h0, l0, h1, l1;
    split2(v.x, v.y, h0, l0);
    split2(v.z, v.w, h1, l1);
    ((uint2*)g_xh)[i] = make_uint2(h0, h1);
    ((uint2*)g_xl)[i] = make_uint2(l0, l1);
}

// transpose+split: w fp32 [K,N] -> [N,K] bf16 hi/lo. W=0 -> w_qkv, W=1 -> w_out
template<int W>
__global__ __launch_bounds__(256)
void cvt_split_T(const float* __restrict__ in, int N)
{
    __shared__ float t[32][33];
    int n0 = blockIdx.x * 32, k0 = blockIdx.y * 32;
    int tx = threadIdx.x, ty = threadIdx.y;   // 32 x 8
    #pragma unroll
    for (int i = 0; i < 4; i++) {
        int k = ty + i * 8;
        t[k][tx] = in[(size_t)(k0 + k) * N + n0 + tx];
    }
    __syncthreads();
    __nv_bfloat16* oh = (W == 0) ? g_wqh : g_woh;
    __nv_bfloat16* ol = (W == 0) ? g_wql : g_wol;
    #pragma unroll
    for (int i = 0; i < 4; i++) {
        int n = ty + i * 8;
        float x = t[tx][n];
        unsigned short hh, ll;
        bf16_split(x, hh, ll);
        size_t o = (size_t)(n0 + n) * GK + k0 + tx;
        oh[o] = __ushort_as_bfloat16(hh);
        ol[o] = __ushort_as_bfloat16(ll);
    }
}

// ===================== double-buffered bf16 HMMA GEMM ======================
// Pre-split operands: A [M,K] hi/lo, B [N,K] hi/lo (K-contiguous).
// C = AhBh + AhBl + AlBh. CTA 128x128, 8 warps 2x4, warp 64x32, BK=16.
// Per stage per thread: 4 uint4 LDG + 4 uint4 STS. No split ALU in-loop.
#define BKS  16
#define NST  (GK / BKS)
#define AST  24    // smem row stride in bf16 (12 words -> conflict-free frags)

template<int MODE>
__global__ __launch_bounds__(256)
void gemm_mma(float* __restrict__ Cp, int N)
{
    __shared__ __nv_bfloat16 sA[2][2][128][AST];   // 24 KB
    __shared__ __nv_bfloat16 sB[2][2][128][AST];   // 24 KB

    const int tid  = threadIdx.x;
    const int wid  = tid >> 5;
    const int lane = tid & 31;
    const int wm   = wid & 1;
    const int wn   = wid >> 1;
    const int gid  = lane >> 2;
    const int tig  = lane & 3;
    const int row0 = blockIdx.y * 128;
    const int col0 = blockIdx.x * 128;

    const __nv_bfloat16* Ah_g = (MODE == 0) ? g_xh : g_ah;
    const __nv_bfloat16* Al_g = (MODE == 0) ? g_xl : g_al;
    const __nv_bfloat16* Bh_g = (MODE == 0) ? g_wqh : g_woh;
    const __nv_bfloat16* Bl_g = (MODE == 0) ? g_wql : g_wol;

    float d[4][4][4];
    #pragma unroll
    for (int i = 0; i < 4; i++)
        #pragma unroll
        for (int j = 0; j < 4; j++)
            #pragma unroll
            for (int e = 0; e < 4; e++) d[i][j][e] = 0.f;

    // tile copy slot: row r8 (0..127), 8-elem chunk co (0 or 8)
    const int r8 = tid >> 1, co = (tid & 1) * 8;
    uint4 vah, val, vbh, vbl;

    // ---- prologue: load + store stage 0 ----
    vah = *(const uint4*)(Ah_g + (size_t)(row0 + r8) * GK + co);
    val = *(const uint4*)(Al_g + (size_t)(row0 + r8) * GK + co);
    vbh = *(const uint4*)(Bh_g + (size_t)(col0 + r8) * GK + co);
    vbl = *(const uint4*)(Bl_g + (size_t)(col0 + r8) * GK + co);
    *(uint4*)&sA[0][0][r8][co] = vah;
    *(uint4*)&sA[0][1][r8][co] = val;
    *(uint4*)&sB[0][0][r8][co] = vbh;
    *(uint4*)&sB[0][1][r8][co] = vbl;
    __syncthreads();

    const int kb = tig * 2;
    for (int kt = 0; kt < NST; kt++) {
        const int buf = kt & 1;
        // ---- prefetch stage kt+1 (LDG in flight during compute) ----
        if (kt + 1 < NST) {
            const int k0 = (kt + 1) * BKS + co;
            vah = *(const uint4*)(Ah_g + (size_t)(row0 + r8) * GK + k0);
            val = *(const uint4*)(Al_g + (size_t)(row0 + r8) * GK + k0);
            vbh = *(const uint4*)(Bh_g + (size_t)(col0 + r8) * GK + k0);
            vbl = *(const uint4*)(Bl_g + (size_t)(col0 + r8) * GK + k0);
        }

        // ---- compute stage kt ----
        uint32_t Ah[4][4], Al[4][4];
        #pragma unroll
        for (int mi = 0; mi < 4; mi++) {
            const int r0 = wm * 64 + mi * 16 + gid;
            Ah[mi][0] = *(const uint32_t*)&sA[buf][0][r0][kb];
            Ah[mi][1] = *(const uint32_t*)&sA[buf][0][r0 + 8][kb];
            Ah[mi][2] = *(const uint32_t*)&sA[buf][0][r0][kb + 8];
            Ah[mi][3] = *(const uint32_t*)&sA[buf][0][r0 + 8][kb + 8];
            Al[mi][0] = *(const uint32_t*)&sA[buf][1][r0][kb];
            Al[mi][1] = *(const uint32_t*)&sA[buf][1][r0 + 8][kb];
            Al[mi][2] = *(const uint32_t*)&sA[buf][1][r0][kb + 8];
            Al[mi][3] = *(const uint32_t*)&sA[buf][1][r0 + 8][kb + 8];
        }
        uint32_t Bh[4][2], Bl[4][2];
        #pragma unroll
        for (int ng = 0; ng < 4; ng++) {
            const int nr = wn * 32 + ng * 8 + gid;
            Bh[ng][0] = *(const uint32_t*)&sB[buf][0][nr][kb];
            Bh[ng][1] = *(const uint32_t*)&sB[buf][0][nr][kb + 8];
            Bl[ng][0] = *(const uint32_t*)&sB[buf][1][nr][kb];
            Bl[ng][1] = *(const uint32_t*)&sB[buf][1][nr][kb + 8];
        }
        #pragma unroll
        for (int mi = 0; mi < 4; mi++)
            #pragma unroll
            for (int ng = 0; ng < 4; ng++) {
                MMA_BF16(d[mi][ng], Ah[mi], Bh[ng][0], Bh[ng][1]);
                MMA_BF16(d[mi][ng], Ah[mi], Bl[ng][0], Bl[ng][1]);
                MMA_BF16(d[mi][ng], Al[mi], Bh[ng][0], Bh[ng][1]);
            }

        // ---- store stage kt+1 ----
        if (kt + 1 < NST) {
            const int nb = buf ^ 1;
            *(uint4*)&sA[nb][0][r8][co] = vah;
            *(uint4*)&sA[nb][1][r8][co] = val;
            *(uint4*)&sB[nb][0][r8][co] = vbh;
            *(uint4*)&sB[nb][1][r8][co] = vbl;
        }
        __syncthreads();
    }

    // ---------------- epilogue ----------------
    #pragma unroll
    for (int mi = 0; mi < 4; mi++)
        #pragma unroll
        for (int ng = 0; ng < 4; ng++) {
            const int n = col0 + wn * 32 + ng * 8 + tig * 2;
            #pragma unroll
            for (int h = 0; h < 2; h++) {
                const int m = row0 + wm * 64 + mi * 16 + gid + h * 8;
                float2 v;
                v.x = d[mi][ng][h * 2 + 0];
                v.y = d[mi][ng][h * 2 + 1];
                if (MODE == 0) {
                    const int b = m >> 11, t = m & (T_ - 1);
                    const int sidx = n >> 10;
                    const int dmi  = n & (D_MODEL - 1);
                    const int hh = dmi >> 6, dk = dmi & (DKH - 1);
                    const int bh = (b << 4) + hh;
                    if (sidx == 0) {            // Q: pre-scale + split
                        uint32_t hi, lo;
                        split2(0.125f * v.x, 0.125f * v.y, hi, lo);
                        const size_t idx = ((size_t)bh * T_ + t) * DKH + dk;
                        *(uint32_t*)&g_qh[idx] = hi;
                        *(uint32_t*)&g_ql[idx] = lo;
                    } else if (sidx == 1) {     // K: split
                        uint32_t hi, lo;
                        split2(v.x, v.y, hi, lo);
                        const size_t idx = ((size_t)bh * T_ + t) * DKH + dk;
                        *(uint32_t*)&g_kh[idx] = hi;
                        *(uint32_t*)&g_kl[idx] = lo;
                    } else {                    // V: split + transpose to [dk][t]
                        unsigned short h0, l0, h1, l1;
                        bf16_split(v.x, h0, l0);
                        bf16_split(v.y, h1, l1);
                        const size_t i0 = ((size_t)bh * DKH + dk) * T_ + t;
                        g_vh[i0] = __ushort_as_bfloat16(h0);
                        g_vl[i0] = __ushort_as_bfloat16(l0);
                        g_vh[i0 + T_] = __ushort_as_bfloat16(h1);
                        g_vl[i0 + T_] = __ushort_as_bfloat16(l1);
                    }
                } else {
                    *(float2*)(Cp + (size_t)m * N + n) = v;
                }
            }
        }
}

// ===================== bf16 HMMA causal flash attention ====================
// 128 q-rows/CTA, 8 warps x 16 rows, 64-key tiles. Pre-split inputs.
// Epilogue writes attn output PRE-SPLIT to g_ah/g_al for gemm<1>.
#define VST 72

__global__ __launch_bounds__(256, 2)
void attn_mma()
{
    __shared__ __align__(16) __nv_bfloat16 sKh[64][VST], sKl[64][VST];
    __shared__ __align__(16) __nv_bfloat16 sVh[64][VST], sVl[64][VST];

    const int bh  = blockIdx.y;
    const int q0  = blockIdx.x * 128;
    const int tid = threadIdx.x;
    const int wid = tid >> 5;
    const int lane = tid & 31;
    const int gid = lane >> 2;
    const int tig = lane & 3;

    const __nv_bfloat16* Qh_g = g_qh + ((size_t)bh * T_ + q0) * DKH;
    const __nv_bfloat16* Ql_g = g_ql + ((size_t)bh * T_ + q0) * DKH;
    const __nv_bfloat16* Kh_g = g_kh + (size_t)bh * T_ * DKH;
    const __nv_bfloat16* Kl_g = g_kl + (size_t)bh * T_ * DKH;
    const __nv_bfloat16* Vh_g = g_vh + (size_t)bh * DKH * T_;
    const __nv_bfloat16* Vl_g = g_vl + (size_t)bh * DKH * T_;
    const float LOG2E = 1.4426950408889634f;

    // ---- Q fragments (staged through sKh/sKl in two 64-row passes) ----
    uint32_t Qh[4][4], Ql[4][4];
    #pragma unroll
    for (int pass = 0; pass < 2; pass++) {
        #pragma unroll
        for (int i = 0; i < 2; i++) {
            const int c = tid + i * 256;
            const int rr = c >> 3, cc = (c & 7) * 8;
            *(uint4*)&sKh[rr][cc] = *(const uint4*)(Qh_g + (size_t)(pass * 64 + rr) * DKH + cc);
            *(uint4*)&sKl[rr][cc] = *(const uint4*)(Ql_g + (size_t)(pass * 64 + rr) * DKH + cc);
        }
        __syncthreads();
        if ((wid >> 2) == pass) {
            const int rb = (wid & 3) * 16 + gid;
            #pragma unroll
            for (int ks = 0; ks < 4; ks++) {
                const int kb = ks * 16 + tig * 2;
                Qh[ks][0] = *(const uint32_t*)&sKh[rb][kb];
                Qh[ks][1] = *(const uint32_t*)&sKh[rb + 8][kb];
                Qh[ks][2] = *(const uint32_t*)&sKh[rb][kb + 8];
                Qh[ks][3] = *(const uint32_t*)&sKh[rb + 8][kb + 8];
                Ql[ks][0] = *(const uint32_t*)&sKl[rb][kb];
                Ql[ks][1] = *(const uint32_t*)&sKl[rb + 8][kb];
                Ql[ks][2] = *(const uint32_t*)&sKl[rb][kb + 8];
                Ql[ks][3] = *(const uint32_t*)&sKl[rb + 8][kb + 8];
            }
        }
        __syncthreads();
    }

    float O[8][4];
    #pragma unroll
    for (int i = 0; i < 8; i++)
        #pragma unroll
        for (int e = 0; e < 4; e++) O[i][e] = 0.f;
    float mr[2] = {-1e30f, -1e30f}, lr[2] = {0.f, 0.f};

    const int qA = q0 + wid * 16 + gid;
    const int ntiles = (q0 >> 6) + 2;

    for (int t = 0; t < ntiles; t++) {
        const int k0 = t * 64;
        uint4 kh[2], kl[2], vh[2], vl[2];
        #pragma unroll
        for (int i = 0; i < 2; i++) {
            const int c = tid + i * 256;
            const int rr = c >> 3, cc = (c & 7) * 8;
            kh[i] = *(const uint4*)(Kh_g + (size_t)(k0 + rr) * DKH + cc);
            kl[i] = *(const uint4*)(Kl_g + (size_t)(k0 + rr) * DKH + cc);
            vh[i] = *(const uint4*)(Vh_g + (size_t)rr * T_ + k0 + cc);
            vl[i] = *(const uint4*)(Vl_g + (size_t)rr * T_ + k0 + cc);
        }
        __syncthreads();
        #pragma unroll
        for (int i = 0; i < 2; i++) {
            const int c = tid + i * 256;
            const int rr = c >> 3, cc = (c & 7) * 8;
            *(uint4*)&sKh[rr][cc] = kh[i];
            *(uint4*)&sKl[rr][cc] = kl[i];
            *(uint4*)&sVh[rr][cc] = vh[i];
            *(uint4*)&sVl[rr][cc] = vl[i];
        }
        __syncthreads();

        if (k0 <= q0 + wid * 16 + 15) {
            float S[8][4];
            #pragma unroll
            for (int i = 0; i < 8; i++)
                #pragma unroll
                for (int e = 0; e < 4; e++) S[i][e] = 0.f;
            #pragma unroll
            for (int ks = 0; ks < 4; ks++) {
                const int kb = ks * 16 + tig * 2;
                #pragma unroll
                for (int ng = 0; ng < 8; ng++) {
                    const int nr = ng * 8 + gid;
                    uint32_t bh0 = *(const uint32_t*)&sKh[nr][kb];
                    uint32_t bh1 = *(const uint32_t*)&sKh[nr][kb + 8];
                    uint32_t bl0 = *(const uint32_t*)&sKl[nr][kb];
                    uint32_t bl1 = *(const uint32_t*)&sKl[nr][kb + 8];
                    MMA_BF16(S[ng], Qh[ks], bh0, bh1);
                    MMA_BF16(S[ng], Qh[ks], bl0, bl1);
                    MMA_BF16(S[ng], Ql[ks], bh0, bh1);
                }
            }
            if (k0 + 63 > q0 + wid * 16) {
                #pragma unroll
                for (int ng = 0; ng < 8; ng++)
                    #pragma unroll
                    for (int e = 0; e < 4; e++) {
                        const int key = k0 + ng * 8 + tig * 2 + (e & 1);
                        const int q   = qA + (e >> 1) * 8;
                        if (key > q) S[ng][e] = -1e30f;
                    }
            }
            #pragma unroll
            for (int h = 0; h < 2; h++) {
                float mt = -1e30f;
                #pragma unroll
                for (int ng = 0; ng < 8; ng++)
                    mt = fmaxf(mt, fmaxf(S[ng][2 * h], S[ng][2 * h + 1]));
                mt = fmaxf(mt, __shfl_xor_sync(0xffffffff, mt, 1));
                mt = fmaxf(mt, __shfl_xor_sync(0xffffffff, mt, 2));
                const float mn = fmaxf(mr[h], mt);
                const float alpha = exp2f((mr[h] - mn) * LOG2E);
                float rs = 0.f;
                #pragma unroll
                for (int ng = 0; ng < 8; ng++) {
                    float p0 = exp2f((S[ng][2 * h] - mn) * LOG2E);
                    float p1 = exp2f((S[ng][2 * h + 1] - mn) * LOG2E);
                    S[ng][2 * h] = p0;
                    S[ng][2 * h + 1] = p1;
                    rs += p0 + p1;
                }
                rs += __shfl_xor_sync(0xffffffff, rs, 1);
                rs += __shfl_xor_sync(0xffffffff, rs, 2);
                lr[h] = lr[h] * alpha + rs;
                mr[h] = mn;
                #pragma unroll
                for (int ng = 0; ng < 8; ng++) {
                    O[ng][2 * h] *= alpha;
                    O[ng][2 * h + 1] *= alpha;
                }
            }
            #pragma unroll
            for (int ks = 0; ks < 4; ks++) {
                uint32_t Ph[4], Pl[4];
                split2(S[2 * ks][0],     S[2 * ks][1],     Ph[0], Pl[0]);
                split2(S[2 * ks][2],     S[2 * ks][3],     Ph[1], Pl[1]);
                split2(S[2 * ks + 1][0], S[2 * ks + 1][1], Ph[2], Pl[2]);
                split2(S[2 * ks + 1][2], S[2 * ks + 1][3], Ph[3], Pl[3]);
                const int kb = ks * 16 + tig * 2;
                #pragma unroll
                for (int ng = 0; ng < 8; ng++) {
                    const int nr = ng * 8 + gid;
                    uint32_t vh0 = *(const uint32_t*)&sVh[nr][kb];
                    uint32_t vh1 = *(const uint32_t*)&sVh[nr][kb + 8];
                    uint32_t vl0 = *(const uint32_t*)&sVl[nr][kb];
                    uint32_t vl1 = *(const uint32_t*)&sVl[nr][kb + 8];
                    MMA_BF16(O[ng], Ph, vh0, vh1);
                    MMA_BF16(O[ng], Ph, vl0, vl1);
                    MMA_BF16(O[ng], Pl, vh0, vh1);
                }
            }
        }
    }

    // ---- epilogue: normalize + PRE-SPLIT write to g_ah/g_al (B,T,D) ----
    const int b = bh >> 4, h = bh & 15;
    #pragma unroll
    for (int hh = 0; hh < 2; hh++) {
        const float inv = 1.f / lr[hh];
        const int q = qA + hh * 8;
        const size_t base = ((size_t)(b * T_ + q)) * D_MODEL + h * DKH;
        #pragma unroll
        for (int ng = 0; ng < 8; ng++) {
            uint32_t hi, lo;
            split2(O[ng][2 * hh] * inv, O[ng][2 * hh + 1] * inv, hi, lo);
            *(uint32_t*)&g_ah[base + ng * 8 + tig * 2] = hi;
            *(uint32_t*)&g_al[base + ng * 8 + tig * 2] = lo;
        }
    }
}

// ---------------------------------------------------------------------------
extern "C" void kernel_launch(void* const* d_in, const int* in_sizes, int n_in,
                              void* d_out, int out_size)
{
    const float* x     = (const float*)d_in[0];
    const float* w_qkv = (const float*)d_in[1];
    const float* w_out = (const float*)d_in[2];
    float* out = (float*)d_out;

    // pre-split inputs (globals referenced inside kernels)
    cvt_split<<<(M_TOT * GK / 4 + 255) / 256, 256>>>(x, M_TOT * GK / 4);
    cvt_split_T<0><<<dim3(N_QKV / 32, GK / 32), dim3(32, 8)>>>(w_qkv, N_QKV);
    cvt_split_T<1><<<dim3(D_MODEL / 32, GK / 32), dim3(32, 8)>>>(w_out, D_MODEL);

    gemm_mma<0><<<dim3(N_QKV / 128, M_TOT / 128), 256>>>(nullptr, N_QKV);
    attn_mma<<<dim3(T_ / 128, B_ * N_HEADS), 256>>>();
    gemm_mma<1><<<dim3(D_MODEL / 128, M_TOT / 128), 256>>>(out, D_MODEL);
}